// round 12
// baseline (speedup 1.0000x reference)
#include <cuda_runtime.h>
#include <cuda_fp16.h>
#include <cstdint>

// Shapes: N=100000, D=64, H=128, E=1600000
#define Dk     64
#define Hk     128
#define TE     128      // edges per tile
#define PH     144      // US/VS/W2S pitch in halves (conflict-free LDS.64)
#define PU     80       // uv-kernel smem pitch in halves (40 words ≡ 8 mod 32)
#define MAXN   100000

// Scratch: U = nodes @ W1[:64,:], V = nodes @ W1[64:,:]  (fp16, k-permuted cols)
__device__ __half g_U[(size_t)MAXN * Hk];
__device__ __half g_V[(size_t)MAXN * Hk];

// per-16-group permutation: stored position p holds original unit (p&~15)+c_p16[p&15]
// -> lane q's fragment quad {2q,2q+1,2q+8,2q+9} sits at stored positions 4q..4q+3
__device__ __constant__ int c_p16[16] = {0,1,8,9, 2,3,10,11, 4,5,12,13, 6,7,14,15};

// ---------------- smem BYTE layout for edge kernel ----------------
#define B_US   0                          // half[128*PH]
#define B_VS   (B_US + TE * PH * 2)       // half[128*PH]
#define B_W2   (B_VS + TE * PH * 2)       // half[64*PH]
#define B_B2   (B_W2 + Dk * PH * 2)       // float[64]
#define B_EIS  (B_B2 + Dk * 4)            // int[128]
#define B_EJS  (B_EIS + TE * 4)           // int[128]
#define EDGE_SMEM_BYTES (B_EJS + TE * 4)

// ---------------- smem BYTE layout for uv mma kernel ----------------
#define UB_A   0                          // half[64*PU]   (node tile, D k-permuted)
#define UB_B   (UB_A + 64 * PU * 2)       // half[256*PU]  (W1^T, D k-permuted, H col-permuted)
#define UV_SMEM_BYTES (UB_B + 256 * PU * 2)

extern __shared__ char smem_raw[];

__device__ __forceinline__ uint32_t smem_u32(const void* p) {
    uint32_t a;
    asm("{ .reg .u64 t; cvta.to.shared.u64 t, %1; cvt.u32.u64 %0, t; }" : "=r"(a) : "l"(p));
    return a;
}
__device__ __forceinline__ void red_add_v4(float* addr, float x, float y, float z, float w) {
    asm volatile("red.global.add.v4.f32 [%0], {%1,%2,%3,%4};"
                 :: "l"(addr), "f"(x), "f"(y), "f"(z), "f"(w) : "memory");
}
__device__ __forceinline__ void cp_async16(void* sdst, const void* gsrc) {
    uint32_t s = smem_u32(sdst);
    asm volatile("cp.async.cg.shared.global [%0], [%1], 16;" :: "r"(s), "l"(gsrc) : "memory");
}
__device__ __forceinline__ void mma_f16(float c[4],
                                        uint32_t a0, uint32_t a1, uint32_t a2, uint32_t a3,
                                        uint32_t b0, uint32_t b1) {
    asm volatile(
        "mma.sync.aligned.m16n8k16.row.col.f32.f16.f16.f32 "
        "{%0,%1,%2,%3}, {%4,%5,%6,%7}, {%8,%9}, {%0,%1,%2,%3};"
        : "+f"(c[0]), "+f"(c[1]), "+f"(c[2]), "+f"(c[3])
        : "r"(a0), "r"(a1), "r"(a2), "r"(a3), "r"(b0), "r"(b1));
}
__device__ __forceinline__ uint32_t relu2add(uint32_t u, uint32_t v, __half2 b) {
    __half2 x = __hadd2(__hadd2(*(__half2*)&u, *(__half2*)&v), b);
    __half2 z = __float2half2_rn(0.f);
    __half2 r = __hmax2(x, z);
    return *(uint32_t*)&r;
}

// ---------------- Kernel 0: out = nodes ----------------
__global__ __launch_bounds__(256) void copy_kernel(const float* __restrict__ nodes,
                                                   float* __restrict__ out, int n4) {
    int i = blockIdx.x * blockDim.x + threadIdx.x;
    if (i < n4) ((float4*)out)[i] = ((const float4*)nodes)[i];
}

// ---------------- Kernel A: U/V precompute via fp16 mma ----------------
// Block = 64 nodes x 256 outputs (U cols 0..127 | V cols 128..255), K = D = 64.
// 8 warps: mt = wid&1 (m32), nh = wid>>1 (n64). Outputs stored as half2 in the
// edge kernel's permuted-column layout.
__global__ __launch_bounds__(256) void uv_kernel(const float* __restrict__ nodes,
                                                 const float* __restrict__ W1, int N) {
    char* smem = smem_raw;
    __half* Ah = (__half*)(smem + UB_A);   // [64][PU]
    __half* Bh = (__half*)(smem + UB_B);   // [256][PU]

    int tid = threadIdx.x, wid = tid >> 5, lane = tid & 31;
    int rr = lane >> 2, q = lane & 3;
    int nbase = blockIdx.x * 64;

    // ---- stage A: Ah[row][kpos] = half(nodes[gn][kperm(kpos)]) ----
    for (int idx = tid; idx < 64 * Dk; idx += 256) {
        int row = idx >> 6, k = idx & 63;
        int kp = (k & ~15) + c_p16[k & 15];
        int gn = nbase + row;
        Ah[row * PU + k] = (gn < N) ? __float2half(nodes[(size_t)gn * Dk + kp])
                                    : __float2half(0.f);
    }
    // ---- stage B: Bh[n][kpos] = half(W1[(n>=128?64:0)+kperm(kpos)][unit(n&127)]) ----
    for (int idx = tid; idx < 256 * Dk; idx += 256) {
        int n = idx >> 6, k = idx & 63;
        int kp = (k & ~15) + c_p16[k & 15];
        int unit = ((n & 127) & ~15) + c_p16[n & 15];
        int w1row = (n >> 7) * 64 + kp;
        Bh[n * PU + k] = __float2half(W1[w1row * Hk + unit]);
    }
    __syncthreads();

    int mt = wid & 1;            // m32 tile
    int n0 = (wid >> 1) * 64;    // n64 tile

    float acc[2][8][4];
    #pragma unroll
    for (int mm = 0; mm < 2; mm++)
        #pragma unroll
        for (int j = 0; j < 8; j++)
            #pragma unroll
            for (int x = 0; x < 4; x++) acc[mm][j][x] = 0.f;

    #pragma unroll
    for (int g = 0; g < 4; g++) {
        int kof = g * 16 + 4 * q;
        uint32_t a[2][4];
        #pragma unroll
        for (int mm = 0; mm < 2; mm++) {
            int base = (mt * 32 + 16 * mm + rr) * PU + kof;
            uint2 x0 = *(const uint2*)(Ah + base);
            uint2 x1 = *(const uint2*)(Ah + base + 8 * PU);
            a[mm][0] = x0.x; a[mm][2] = x0.y;
            a[mm][1] = x1.x; a[mm][3] = x1.y;
        }
        #pragma unroll
        for (int j = 0; j < 8; j++) {
            uint2 bb = *(const uint2*)(Bh + (n0 + 8 * j + rr) * PU + kof);
            #pragma unroll
            for (int mm = 0; mm < 2; mm++)
                mma_f16(acc[mm][j], a[mm][0], a[mm][1], a[mm][2], a[mm][3],
                        bb.x, bb.y);
        }
    }

    // ---- store: half2 into g_U / g_V (whole warp targets one array) ----
    __half* Out = (n0 < 128) ? g_U : g_V;
    int cb = (n0 & 127);
    #pragma unroll
    for (int mm = 0; mm < 2; mm++) {
        int r0 = nbase + mt * 32 + 16 * mm + rr;
        #pragma unroll
        for (int j = 0; j < 8; j++) {
            int col = cb + 8 * j + 2 * q;
            if (r0 < N) {
                __half2 h = __floats2half2_rn(acc[mm][j][0], acc[mm][j][1]);
                *(__half2*)&Out[(size_t)r0 * Hk + col] = h;
            }
            if (r0 + 8 < N) {
                __half2 h = __floats2half2_rn(acc[mm][j][2], acc[mm][j][3]);
                *(__half2*)&Out[(size_t)(r0 + 8) * Hk + col] = h;
            }
        }
    }
}

// ---------------- Kernel B: persistent edge kernel, fp16 mma ----------
__global__ __launch_bounds__(256, 2) void edge_kernel(const int* __restrict__ edges,
                                                      const float* __restrict__ W2,
                                                      const float* __restrict__ b1,
                                                      const float* __restrict__ b2,
                                                      float* __restrict__ out,
                                                      int E, int tiles) {
    char* smem = smem_raw;
    __half* USh = (__half*)(smem + B_US);
    __half* VSh = (__half*)(smem + B_VS);
    __half* W2h = (__half*)(smem + B_W2);
    float*  b2s = (float*)(smem + B_B2);
    int*    eis = (int*)(smem + B_EIS);
    int*    ejs = (int*)(smem + B_EJS);

    int tid = threadIdx.x, wid = tid >> 5, lane = tid & 31;
    int rr = lane >> 2, q = lane & 3;
    int s = q & 1, tq = q >> 1;

    // ---- one-time staging ----
    for (int idx = tid; idx < Hk * Dk; idx += 256) {
        int k = idx >> 6, n = idx & 63;
        int unit = (k & ~15) + c_p16[k & 15];
        W2h[n * PH + k] = __float2half(W2[unit * Dk + n]);
    }
    if (tid < Dk) b2s[tid] = b2[tid];

    __half2 b1lo[8], b1hi[8];
    #pragma unroll
    for (int g = 0; g < 8; g++) {
        b1lo[g] = __floats2half2_rn(b1[g * 16 + 2 * q],     b1[g * 16 + 2 * q + 1]);
        b1hi[g] = __floats2half2_rn(b1[g * 16 + 2 * q + 8], b1[g * 16 + 2 * q + 9]);
    }
    __syncthreads();

    int er0 = (wid & 3) * 32;
    int n0  = (wid >> 2) * 32;

    int l16 = lane & 15, h16 = lane >> 4;

    for (int t = blockIdx.x; t < tiles; t += gridDim.x) {
        int ebase = t * TE;
        if (tid < TE) {
            int e = ebase + tid;
            int a = 0, b = 0;
            if (e < E) { a = edges[2 * e]; b = edges[2 * e + 1]; }
            eis[tid] = a; ejs[tid] = b;
        }
        __syncthreads();

        #pragma unroll
        for (int dir = 0; dir < 2; dir++) {
            const int* sn = dir ? ejs : eis;
            const int* on = dir ? eis : ejs;

            #pragma unroll
            for (int r0 = wid * 16; r0 < wid * 16 + 16; r0 += 2) {
                int row = r0 + h16;
                const __half* up = g_U + (size_t)sn[row] * Hk;
                const __half* vp = g_V + (size_t)on[row] * Hk;
                cp_async16(USh + row * PH + l16 * 8, up + l16 * 8);
                cp_async16(VSh + row * PH + l16 * 8, vp + l16 * 8);
            }
            asm volatile("cp.async.commit_group;" ::: "memory");
            asm volatile("cp.async.wait_group 0;" ::: "memory");
            __syncthreads();

            float acc[2][4][4];
            #pragma unroll
            for (int mm = 0; mm < 2; mm++)
                #pragma unroll
                for (int j = 0; j < 4; j++)
                    #pragma unroll
                    for (int x = 0; x < 4; x++) acc[mm][j][x] = 0.f;

            #pragma unroll
            for (int g = 0; g < 8; g++) {
                int kof = g * 16 + 4 * q;
                uint32_t a[2][4];
                #pragma unroll
                for (int mm = 0; mm < 2; mm++) {
                    int base = (er0 + 16 * mm + rr) * PH + kof;
                    uint2 u0 = *(const uint2*)(USh + base);
                    uint2 v0 = *(const uint2*)(VSh + base);
                    uint2 u1 = *(const uint2*)(USh + base + 8 * PH);
                    uint2 v1 = *(const uint2*)(VSh + base + 8 * PH);
                    a[mm][0] = relu2add(u0.x, v0.x, b1lo[g]);
                    a[mm][2] = relu2add(u0.y, v0.y, b1hi[g]);
                    a[mm][1] = relu2add(u1.x, v1.x, b1lo[g]);
                    a[mm][3] = relu2add(u1.y, v1.y, b1hi[g]);
                }
                #pragma unroll
                for (int j = 0; j < 4; j++) {
                    uint2 bb = *(const uint2*)(W2h + (n0 + 8 * j + rr) * PH + kof);
                    #pragma unroll
                    for (int mm = 0; mm < 2; mm++)
                        mma_f16(acc[mm][j], a[mm][0], a[mm][1], a[mm][2], a[mm][3],
                                bb.x, bb.y);
                }
            }

            #pragma unroll
            for (int j = 0; j < 4; j++) {
                int nb = n0 + 8 * j + 2 * q;
                float bx = b2s[nb], by = b2s[nb + 1];
                #pragma unroll
                for (int mm = 0; mm < 2; mm++) {
                    acc[mm][j][0] += bx; acc[mm][j][1] += by;
                    acc[mm][j][2] += bx; acc[mm][j][3] += by;
                }
            }
            #pragma unroll
            for (int mm = 0; mm < 2; mm++) {
                int er = er0 + 16 * mm + rr + 8 * s;
                bool valid = (ebase + er) < E;
                int node = valid ? sn[er] : 0;
                float* base = out + (size_t)node * Dk;
                #pragma unroll
                for (int j = 0; j < 4; j++) {
                    float y0 = __shfl_xor_sync(0xffffffffu,
                                   s ? acc[mm][j][0] : acc[mm][j][2], 1);
                    float y1 = __shfl_xor_sync(0xffffffffu,
                                   s ? acc[mm][j][1] : acc[mm][j][3], 1);
                    float p0 = s ? y0 : acc[mm][j][0];
                    float p1 = s ? y1 : acc[mm][j][1];
                    float p2 = s ? acc[mm][j][2] : y0;
                    float p3 = s ? acc[mm][j][3] : y1;
                    if (valid) {
                        int nb = n0 + 8 * j + 4 * tq;
                        red_add_v4(base + nb, p0, p1, p2, p3);
                    }
                }
            }
            __syncthreads();
        }
    }
}

extern "C" void kernel_launch(void* const* d_in, const int* in_sizes, int n_in,
                              void* d_out, int out_size) {
    const float* nodes = (const float*)d_in[0];
    const int*   edges = (const int*)d_in[1];
    const float* W1    = (const float*)d_in[2];
    const float* b1    = (const float*)d_in[3];
    const float* W2    = (const float*)d_in[4];
    const float* b2    = (const float*)d_in[5];
    float* out = (float*)d_out;

    int N = in_sizes[0] / Dk;
    int E = in_sizes[1] / 2;

    static int nsm = 0;
    if (!nsm) {
        cudaDeviceGetAttribute(&nsm, cudaDevAttrMultiProcessorCount, 0);
        cudaFuncSetAttribute(uv_kernel,   cudaFuncAttributeMaxDynamicSharedMemorySize, UV_SMEM_BYTES);
        cudaFuncSetAttribute(edge_kernel, cudaFuncAttributeMaxDynamicSharedMemorySize, EDGE_SMEM_BYTES);
    }

    int n4 = (N * Dk) / 4;
    copy_kernel<<<(n4 + 255) / 256, 256>>>(nodes, out, n4);

    int uv_blocks = (N + 63) / 64;
    uv_kernel<<<uv_blocks, 256, UV_SMEM_BYTES>>>(nodes, W1, N);

    int tiles = (E + TE - 1) / TE;
    edge_kernel<<<2 * nsm, 256, EDGE_SMEM_BYTES>>>(edges, W2, b1, b2, out, E, tiles);
}

// round 13
// speedup vs baseline: 1.2235x; 1.2235x over previous
#include <cuda_runtime.h>
#include <cuda_fp16.h>
#include <cstdint>

// Shapes: N=100000, D=64, H=128, E=1600000
#define Dk     64
#define Hk     128
#define TE     128      // edges per tile
#define PH     144      // US/VS/W2S pitch in halves (conflict-free LDS.64)
#define PU     80       // uv-kernel smem pitch in halves
#define MAXN   100000

// Scratch: U = nodes @ W1[:64,:], V = nodes @ W1[64:,:]  (fp16, k-permuted cols)
__device__ __half g_U[(size_t)MAXN * Hk];
__device__ __half g_V[(size_t)MAXN * Hk];
// Prepped operands for uv_kernel
__device__ __half g_Nh[(size_t)MAXN * Dk];     // fp16 nodes, k-permuted
__device__ __half g_W1h[256 * Dk];             // fp16 W1 in B layout

// per-16-group permutation: stored position p holds original unit (p&~15)+c_p16[p&15]
__device__ __constant__ int c_p16[16] = {0,1,8,9, 2,3,10,11, 4,5,12,13, 6,7,14,15};

// ---------------- smem BYTE layout for edge kernel ----------------
#define B_US   0                          // half[128*PH]
#define B_VS   (B_US + TE * PH * 2)       // half[128*PH]
#define B_W2   (B_VS + TE * PH * 2)       // half[64*PH]
#define B_B2   (B_W2 + Dk * PH * 2)       // float[64]
#define B_EIS  (B_B2 + Dk * 4)            // int[128]
#define B_EJS  (B_EIS + TE * 4)           // int[128]
#define EDGE_SMEM_BYTES (B_EJS + TE * 4)

// ---------------- smem BYTE layout for uv mma kernel ----------------
#define UB_A   0                          // half[64*PU]
#define UB_B   (UB_A + 64 * PU * 2)       // half[256*PU]
#define UV_SMEM_BYTES (UB_B + 256 * PU * 2)

extern __shared__ char smem_raw[];

__device__ __forceinline__ uint32_t smem_u32(const void* p) {
    uint32_t a;
    asm("{ .reg .u64 t; cvta.to.shared.u64 t, %1; cvt.u32.u64 %0, t; }" : "=r"(a) : "l"(p));
    return a;
}
__device__ __forceinline__ void red_add_v4(float* addr, float x, float y, float z, float w) {
    asm volatile("red.global.add.v4.f32 [%0], {%1,%2,%3,%4};"
                 :: "l"(addr), "f"(x), "f"(y), "f"(z), "f"(w) : "memory");
}
__device__ __forceinline__ void cp_async16(void* sdst, const void* gsrc) {
    uint32_t s = smem_u32(sdst);
    asm volatile("cp.async.cg.shared.global [%0], [%1], 16;" :: "r"(s), "l"(gsrc) : "memory");
}
__device__ __forceinline__ void mma_f16(float c[4],
                                        uint32_t a0, uint32_t a1, uint32_t a2, uint32_t a3,
                                        uint32_t b0, uint32_t b1) {
    asm volatile(
        "mma.sync.aligned.m16n8k16.row.col.f32.f16.f16.f32 "
        "{%0,%1,%2,%3}, {%4,%5,%6,%7}, {%8,%9}, {%0,%1,%2,%3};"
        : "+f"(c[0]), "+f"(c[1]), "+f"(c[2]), "+f"(c[3])
        : "r"(a0), "r"(a1), "r"(a2), "r"(a3), "r"(b0), "r"(b1));
}
__device__ __forceinline__ uint32_t relu2add(uint32_t u, uint32_t v, __half2 b) {
    __half2 x = __hadd2(__hadd2(*(__half2*)&u, *(__half2*)&v), b);
    __half2 z = __float2half2_rn(0.f);
    __half2 r = __hmax2(x, z);
    return *(uint32_t*)&r;
}

// ---------------- Kernel 0: out = nodes ----------------
__global__ __launch_bounds__(256) void copy_kernel(const float* __restrict__ nodes,
                                                   float* __restrict__ out, int n4) {
    int i = blockIdx.x * blockDim.x + threadIdx.x;
    if (i < n4) ((float4*)out)[i] = ((const float4*)nodes)[i];
}

// ---------------- Prep 1: nodes -> fp16 k-permuted ----------------
// c_p16 pairs are contiguous (0,1)(8,9)(2,3)... so even k maps to float2 reads.
__global__ __launch_bounds__(256) void prep_nodes(const float* __restrict__ nodes,
                                                  int total2) {
    int i = blockIdx.x * blockDim.x + threadIdx.x;   // half2 units
    if (i >= total2) return;
    int gn = i >> 5;
    int kk = (i & 31) * 2;
    int kp = (kk & ~15) + c_p16[kk & 15];
    float2 v = *(const float2*)&nodes[(size_t)gn * Dk + kp];
    *(__half2*)&g_Nh[(size_t)gn * Dk + kk] = __floats2half2_rn(v.x, v.y);
}

// ---------------- Prep 2: W1 -> fp16 B layout (one-shot) ----------------
__global__ __launch_bounds__(256) void prep_w1(const float* __restrict__ W1) {
    int idx = blockIdx.x * blockDim.x + threadIdx.x;  // 256*64
    if (idx >= 256 * Dk) return;
    int n = idx >> 6, k = idx & 63;
    int kp = (k & ~15) + c_p16[k & 15];
    int unit = ((n & 127) & ~15) + c_p16[n & 15];
    int w1row = (n >> 7) * 64 + kp;
    g_W1h[n * Dk + k] = __float2half(W1[w1row * Hk + unit]);
}

// ---------------- Kernel A: U/V via fp16 mma, cp.async staged ----------------
// Block = 64 nodes x 256 outputs (U cols | V cols), K = 64.
__global__ __launch_bounds__(256) void uv_kernel(int N) {
    char* smem = smem_raw;
    __half* Ah = (__half*)(smem + UB_A);   // [64][PU]
    __half* Bh = (__half*)(smem + UB_B);   // [256][PU]

    int tid = threadIdx.x, wid = tid >> 5, lane = tid & 31;
    int rr = lane >> 2, q = lane & 3;
    int nbase = blockIdx.x * 64;

    // ---- stage A: 64 rows x 128B, coalesced cp.async ----
    #pragma unroll
    for (int i = tid; i < 64 * 8; i += 256) {
        int row = i >> 3, c = i & 7;
        int gn = nbase + row;
        if (gn >= N) gn = N - 1;             // clamp; garbage rows never stored
        cp_async16(Ah + row * PU + c * 8, g_Nh + (size_t)gn * Dk + c * 8);
    }
    // ---- stage B: 256 rows x 128B, coalesced cp.async ----
    #pragma unroll
    for (int i = tid; i < 256 * 8; i += 256) {
        int row = i >> 3, c = i & 7;
        cp_async16(Bh + row * PU + c * 8, g_W1h + row * Dk + c * 8);
    }
    asm volatile("cp.async.commit_group;" ::: "memory");
    asm volatile("cp.async.wait_group 0;" ::: "memory");
    __syncthreads();

    int mt = wid & 1;            // m32 tile
    int n0 = (wid >> 1) * 64;    // n64 tile

    float acc[2][8][4];
    #pragma unroll
    for (int mm = 0; mm < 2; mm++)
        #pragma unroll
        for (int j = 0; j < 8; j++)
            #pragma unroll
            for (int x = 0; x < 4; x++) acc[mm][j][x] = 0.f;

    #pragma unroll
    for (int g = 0; g < 4; g++) {
        int kof = g * 16 + 4 * q;
        uint32_t a[2][4];
        #pragma unroll
        for (int mm = 0; mm < 2; mm++) {
            int base = (mt * 32 + 16 * mm + rr) * PU + kof;
            uint2 x0 = *(const uint2*)(Ah + base);
            uint2 x1 = *(const uint2*)(Ah + base + 8 * PU);
            a[mm][0] = x0.x; a[mm][2] = x0.y;
            a[mm][1] = x1.x; a[mm][3] = x1.y;
        }
        #pragma unroll
        for (int j = 0; j < 8; j++) {
            uint2 bb = *(const uint2*)(Bh + (n0 + 8 * j + rr) * PU + kof);
            #pragma unroll
            for (int mm = 0; mm < 2; mm++)
                mma_f16(acc[mm][j], a[mm][0], a[mm][1], a[mm][2], a[mm][3],
                        bb.x, bb.y);
        }
    }

    // ---- store: half2 into g_U / g_V (permuted-column layout) ----
    __half* Out = (n0 < 128) ? g_U : g_V;
    int cb = (n0 & 127);
    #pragma unroll
    for (int mm = 0; mm < 2; mm++) {
        int r0 = nbase + mt * 32 + 16 * mm + rr;
        #pragma unroll
        for (int j = 0; j < 8; j++) {
            int col = cb + 8 * j + 2 * q;
            if (r0 < N) {
                __half2 h = __floats2half2_rn(acc[mm][j][0], acc[mm][j][1]);
                *(__half2*)&Out[(size_t)r0 * Hk + col] = h;
            }
            if (r0 + 8 < N) {
                __half2 h = __floats2half2_rn(acc[mm][j][2], acc[mm][j][3]);
                *(__half2*)&Out[(size_t)(r0 + 8) * Hk + col] = h;
            }
        }
    }
}

// ---------------- Kernel B: persistent edge kernel, fp16 mma ----------
__global__ __launch_bounds__(256, 2) void edge_kernel(const int* __restrict__ edges,
                                                      const float* __restrict__ W2,
                                                      const float* __restrict__ b1,
                                                      const float* __restrict__ b2,
                                                      float* __restrict__ out,
                                                      int E, int tiles) {
    char* smem = smem_raw;
    __half* USh = (__half*)(smem + B_US);
    __half* VSh = (__half*)(smem + B_VS);
    __half* W2h = (__half*)(smem + B_W2);
    float*  b2s = (float*)(smem + B_B2);
    int*    eis = (int*)(smem + B_EIS);
    int*    ejs = (int*)(smem + B_EJS);

    int tid = threadIdx.x, wid = tid >> 5, lane = tid & 31;
    int rr = lane >> 2, q = lane & 3;
    int s = q & 1, tq = q >> 1;

    for (int idx = tid; idx < Hk * Dk; idx += 256) {
        int k = idx >> 6, n = idx & 63;
        int unit = (k & ~15) + c_p16[k & 15];
        W2h[n * PH + k] = __float2half(W2[unit * Dk + n]);
    }
    if (tid < Dk) b2s[tid] = b2[tid];

    __half2 b1lo[8], b1hi[8];
    #pragma unroll
    for (int g = 0; g < 8; g++) {
        b1lo[g] = __floats2half2_rn(b1[g * 16 + 2 * q],     b1[g * 16 + 2 * q + 1]);
        b1hi[g] = __floats2half2_rn(b1[g * 16 + 2 * q + 8], b1[g * 16 + 2 * q + 9]);
    }
    __syncthreads();

    int er0 = (wid & 3) * 32;
    int n0  = (wid >> 2) * 32;

    int l16 = lane & 15, h16 = lane >> 4;

    for (int t = blockIdx.x; t < tiles; t += gridDim.x) {
        int ebase = t * TE;
        if (tid < TE) {
            int e = ebase + tid;
            int a = 0, b = 0;
            if (e < E) { a = edges[2 * e]; b = edges[2 * e + 1]; }
            eis[tid] = a; ejs[tid] = b;
        }
        __syncthreads();

        #pragma unroll
        for (int dir = 0; dir < 2; dir++) {
            const int* sn = dir ? ejs : eis;
            const int* on = dir ? eis : ejs;

            #pragma unroll
            for (int r0 = wid * 16; r0 < wid * 16 + 16; r0 += 2) {
                int row = r0 + h16;
                const __half* up = g_U + (size_t)sn[row] * Hk;
                const __half* vp = g_V + (size_t)on[row] * Hk;
                cp_async16(USh + row * PH + l16 * 8, up + l16 * 8);
                cp_async16(VSh + row * PH + l16 * 8, vp + l16 * 8);
            }
            asm volatile("cp.async.commit_group;" ::: "memory");
            asm volatile("cp.async.wait_group 0;" ::: "memory");
            __syncthreads();

            float acc[2][4][4];
            #pragma unroll
            for (int mm = 0; mm < 2; mm++)
                #pragma unroll
                for (int j = 0; j < 4; j++)
                    #pragma unroll
                    for (int x = 0; x < 4; x++) acc[mm][j][x] = 0.f;

            #pragma unroll
            for (int g = 0; g < 8; g++) {
                int kof = g * 16 + 4 * q;
                uint32_t a[2][4];
                #pragma unroll
                for (int mm = 0; mm < 2; mm++) {
                    int base = (er0 + 16 * mm + rr) * PH + kof;
                    uint2 u0 = *(const uint2*)(USh + base);
                    uint2 v0 = *(const uint2*)(VSh + base);
                    uint2 u1 = *(const uint2*)(USh + base + 8 * PH);
                    uint2 v1 = *(const uint2*)(VSh + base + 8 * PH);
                    a[mm][0] = relu2add(u0.x, v0.x, b1lo[g]);
                    a[mm][2] = relu2add(u0.y, v0.y, b1hi[g]);
                    a[mm][1] = relu2add(u1.x, v1.x, b1lo[g]);
                    a[mm][3] = relu2add(u1.y, v1.y, b1hi[g]);
                }
                #pragma unroll
                for (int j = 0; j < 4; j++) {
                    uint2 bb = *(const uint2*)(W2h + (n0 + 8 * j + rr) * PH + kof);
                    #pragma unroll
                    for (int mm = 0; mm < 2; mm++)
                        mma_f16(acc[mm][j], a[mm][0], a[mm][1], a[mm][2], a[mm][3],
                                bb.x, bb.y);
                }
            }

            #pragma unroll
            for (int j = 0; j < 4; j++) {
                int nb = n0 + 8 * j + 2 * q;
                float bx = b2s[nb], by = b2s[nb + 1];
                #pragma unroll
                for (int mm = 0; mm < 2; mm++) {
                    acc[mm][j][0] += bx; acc[mm][j][1] += by;
                    acc[mm][j][2] += bx; acc[mm][j][3] += by;
                }
            }
            #pragma unroll
            for (int mm = 0; mm < 2; mm++) {
                int er = er0 + 16 * mm + rr + 8 * s;
                bool valid = (ebase + er) < E;
                int node = valid ? sn[er] : 0;
                float* base = out + (size_t)node * Dk;
                #pragma unroll
                for (int j = 0; j < 4; j++) {
                    float y0 = __shfl_xor_sync(0xffffffffu,
                                   s ? acc[mm][j][0] : acc[mm][j][2], 1);
                    float y1 = __shfl_xor_sync(0xffffffffu,
                                   s ? acc[mm][j][1] : acc[mm][j][3], 1);
                    float p0 = s ? y0 : acc[mm][j][0];
                    float p1 = s ? y1 : acc[mm][j][1];
                    float p2 = s ? acc[mm][j][2] : y0;
                    float p3 = s ? acc[mm][j][3] : y1;
                    if (valid) {
                        int nb = n0 + 8 * j + 4 * tq;
                        red_add_v4(base + nb, p0, p1, p2, p3);
                    }
                }
            }
            __syncthreads();
        }
    }
}

extern "C" void kernel_launch(void* const* d_in, const int* in_sizes, int n_in,
                              void* d_out, int out_size) {
    const float* nodes = (const float*)d_in[0];
    const int*   edges = (const int*)d_in[1];
    const float* W1    = (const float*)d_in[2];
    const float* b1    = (const float*)d_in[3];
    const float* W2    = (const float*)d_in[4];
    const float* b2    = (const float*)d_in[5];
    float* out = (float*)d_out;

    int N = in_sizes[0] / Dk;
    int E = in_sizes[1] / 2;

    static int nsm = 0;
    if (!nsm) {
        cudaDeviceGetAttribute(&nsm, cudaDevAttrMultiProcessorCount, 0);
        cudaFuncSetAttribute(uv_kernel,   cudaFuncAttributeMaxDynamicSharedMemorySize, UV_SMEM_BYTES);
        cudaFuncSetAttribute(edge_kernel, cudaFuncAttributeMaxDynamicSharedMemorySize, EDGE_SMEM_BYTES);
    }

    int n4 = (N * Dk) / 4;
    copy_kernel<<<(n4 + 255) / 256, 256>>>(nodes, out, n4);

    int total2 = N * 32;
    prep_nodes<<<(total2 + 255) / 256, 256>>>(nodes, total2);
    prep_w1<<<(256 * Dk + 255) / 256, 256>>>(W1);

    int uv_blocks = (N + 63) / 64;
    uv_kernel<<<uv_blocks, 256, UV_SMEM_BYTES>>>(N);

    int tiles = (E + TE - 1) / TE;
    edge_kernel<<<2 * nsm, 256, EDGE_SMEM_BYTES>>>(edges, W2, b1, b2, out, E, tiles);
}

// round 14
// speedup vs baseline: 1.2399x; 1.0134x over previous
#include <cuda_runtime.h>
#include <cuda_fp16.h>
#include <cstdint>

// Shapes: N=100000, D=64, H=128, E=1600000
#define Dk     64
#define Hk     128
#define TE     128      // edges per tile
#define PH     144      // US/VS/W2S pitch in halves (conflict-free LDS.64)
#define PU     80       // uv-kernel smem pitch in halves
#define MAXN   100000

// Scratch: U = nodes @ W1[:64,:], V = nodes @ W1[64:,:]  (fp16, k-permuted cols)
__device__ __half g_U[(size_t)MAXN * Hk];
__device__ __half g_V[(size_t)MAXN * Hk];
// Prepped operands for uv_kernel
__device__ __half g_Nh[(size_t)MAXN * Dk];     // fp16 nodes, k-permuted
__device__ __half g_W1h[256 * Dk];             // fp16 W1 in B layout

// per-16-group permutation: stored position p holds original unit (p&~15)+c_p16[p&15]
__device__ __constant__ int c_p16[16] = {0,1,8,9, 2,3,10,11, 4,5,12,13, 6,7,14,15};

// ---------------- smem BYTE layout for edge kernel ----------------
#define B_US   0                          // half[128*PH]
#define B_VS   (B_US + TE * PH * 2)       // half[128*PH]
#define B_W2   (B_VS + TE * PH * 2)       // half[64*PH]
#define B_B2   (B_W2 + Dk * PH * 2)       // float[64]
#define B_EIS  (B_B2 + Dk * 4)            // int[128]
#define B_EJS  (B_EIS + TE * 4)           // int[128]
#define EDGE_SMEM_BYTES (B_EJS + TE * 4)

// ---------------- smem BYTE layout for uv mma kernel ----------------
#define UB_A   0                          // half[64*PU]
#define UB_B   (UB_A + 64 * PU * 2)       // half[256*PU]
#define UV_SMEM_BYTES (UB_B + 256 * PU * 2)

extern __shared__ char smem_raw[];

__device__ __forceinline__ uint32_t smem_u32(const void* p) {
    uint32_t a;
    asm("{ .reg .u64 t; cvta.to.shared.u64 t, %1; cvt.u32.u64 %0, t; }" : "=r"(a) : "l"(p));
    return a;
}
__device__ __forceinline__ void red_add_v4(float* addr, float x, float y, float z, float w) {
    asm volatile("red.global.add.v4.f32 [%0], {%1,%2,%3,%4};"
                 :: "l"(addr), "f"(x), "f"(y), "f"(z), "f"(w) : "memory");
}
__device__ __forceinline__ void cp_async16(void* sdst, const void* gsrc) {
    uint32_t s = smem_u32(sdst);
    asm volatile("cp.async.cg.shared.global [%0], [%1], 16;" :: "r"(s), "l"(gsrc) : "memory");
}
__device__ __forceinline__ void mma_f16(float c[4],
                                        uint32_t a0, uint32_t a1, uint32_t a2, uint32_t a3,
                                        uint32_t b0, uint32_t b1) {
    asm volatile(
        "mma.sync.aligned.m16n8k16.row.col.f32.f16.f16.f32 "
        "{%0,%1,%2,%3}, {%4,%5,%6,%7}, {%8,%9}, {%0,%1,%2,%3};"
        : "+f"(c[0]), "+f"(c[1]), "+f"(c[2]), "+f"(c[3])
        : "r"(a0), "r"(a1), "r"(a2), "r"(a3), "r"(b0), "r"(b1));
}
__device__ __forceinline__ uint32_t relu2add(uint32_t u, uint32_t v, __half2 b) {
    __half2 x = __hadd2(__hadd2(*(__half2*)&u, *(__half2*)&v), b);
    __half2 z = __float2half2_rn(0.f);
    __half2 r = __hmax2(x, z);
    return *(uint32_t*)&r;
}

// ---------------- Prep 1 (fused): out = nodes  AND  g_Nh = fp16 k-permuted ----
// c_p16 maps aligned pairs to aligned pairs bijectively, so reading float2 at kp
// and writing it back at kp covers the identity copy exactly once per element.
__global__ __launch_bounds__(256) void prep_nodes(const float* __restrict__ nodes,
                                                  float* __restrict__ out, int total2) {
    int i = blockIdx.x * blockDim.x + threadIdx.x;   // half2 units
    if (i >= total2) return;
    int gn = i >> 5;
    int kk = (i & 31) * 2;
    int kp = (kk & ~15) + c_p16[kk & 15];
    float2 v = *(const float2*)&nodes[(size_t)gn * Dk + kp];
    *(float2*)&out[(size_t)gn * Dk + kp] = v;                       // identity copy
    *(__half2*)&g_Nh[(size_t)gn * Dk + kk] = __floats2half2_rn(v.x, v.y);
}

// ---------------- Prep 2: W1 -> fp16 B layout (one-shot) ----------------
__global__ __launch_bounds__(256) void prep_w1(const float* __restrict__ W1) {
    int idx = blockIdx.x * blockDim.x + threadIdx.x;  // 256*64
    if (idx >= 256 * Dk) return;
    int n = idx >> 6, k = idx & 63;
    int kp = (k & ~15) + c_p16[k & 15];
    int unit = ((n & 127) & ~15) + c_p16[n & 15];
    int w1row = (n >> 7) * 64 + kp;
    g_W1h[n * Dk + k] = __float2half(W1[w1row * Hk + unit]);
}

// ---------------- Kernel A: U/V via fp16 mma, 4 node-tiles per block ----------
// Block = 256 nodes (4 sub-tiles of 64) x 256 outputs; B staged ONCE per block.
__global__ __launch_bounds__(256) void uv_kernel(int N) {
    char* smem = smem_raw;
    __half* Ah = (__half*)(smem + UB_A);   // [64][PU]
    __half* Bh = (__half*)(smem + UB_B);   // [256][PU]

    int tid = threadIdx.x, wid = tid >> 5, lane = tid & 31;
    int rr = lane >> 2, q = lane & 3;
    int nbase0 = blockIdx.x * 256;

    // ---- stage B once: 256 rows x 128B, coalesced cp.async ----
    #pragma unroll
    for (int i = tid; i < 256 * 8; i += 256) {
        int row = i >> 3, c = i & 7;
        cp_async16(Bh + row * PU + c * 8, g_W1h + row * Dk + c * 8);
    }

    int mt = wid & 1;            // m32 tile
    int n0 = (wid >> 1) * 64;    // n64 tile
    __half* Out = (n0 < 128) ? g_U : g_V;
    int cb = (n0 & 127);

    #pragma unroll 1
    for (int tt = 0; tt < 4; tt++) {
        int nbase = nbase0 + tt * 64;
        if (nbase >= N) break;

        // ---- stage A sub-tile: 64 rows x 128B ----
        #pragma unroll
        for (int i = tid; i < 64 * 8; i += 256) {
            int row = i >> 3, c = i & 7;
            int gn = nbase + row;
            if (gn >= N) gn = N - 1;          // clamp; garbage rows never stored
            cp_async16(Ah + row * PU + c * 8, g_Nh + (size_t)gn * Dk + c * 8);
        }
        asm volatile("cp.async.commit_group;" ::: "memory");
        asm volatile("cp.async.wait_group 0;" ::: "memory");
        __syncthreads();

        float acc[2][8][4];
        #pragma unroll
        for (int mm = 0; mm < 2; mm++)
            #pragma unroll
            for (int j = 0; j < 8; j++)
                #pragma unroll
                for (int x = 0; x < 4; x++) acc[mm][j][x] = 0.f;

        #pragma unroll
        for (int g = 0; g < 4; g++) {
            int kof = g * 16 + 4 * q;
            uint32_t a[2][4];
            #pragma unroll
            for (int mm = 0; mm < 2; mm++) {
                int base = (mt * 32 + 16 * mm + rr) * PU + kof;
                uint2 x0 = *(const uint2*)(Ah + base);
                uint2 x1 = *(const uint2*)(Ah + base + 8 * PU);
                a[mm][0] = x0.x; a[mm][2] = x0.y;
                a[mm][1] = x1.x; a[mm][3] = x1.y;
            }
            #pragma unroll
            for (int j = 0; j < 8; j++) {
                uint2 bb = *(const uint2*)(Bh + (n0 + 8 * j + rr) * PU + kof);
                #pragma unroll
                for (int mm = 0; mm < 2; mm++)
                    mma_f16(acc[mm][j], a[mm][0], a[mm][1], a[mm][2], a[mm][3],
                            bb.x, bb.y);
            }
        }

        // ---- store: half2 into g_U / g_V (permuted-column layout) ----
        #pragma unroll
        for (int mm = 0; mm < 2; mm++) {
            int r0 = nbase + mt * 32 + 16 * mm + rr;
            #pragma unroll
            for (int j = 0; j < 8; j++) {
                int col = cb + 8 * j + 2 * q;
                if (r0 < N) {
                    __half2 h = __floats2half2_rn(acc[mm][j][0], acc[mm][j][1]);
                    *(__half2*)&Out[(size_t)r0 * Hk + col] = h;
                }
                if (r0 + 8 < N) {
                    __half2 h = __floats2half2_rn(acc[mm][j][2], acc[mm][j][3]);
                    *(__half2*)&Out[(size_t)(r0 + 8) * Hk + col] = h;
                }
            }
        }
        __syncthreads();   // Ah free for next sub-tile
    }
}

// ---------------- Kernel B: persistent edge kernel, fp16 mma (unchanged) ------
__global__ __launch_bounds__(256, 2) void edge_kernel(const int* __restrict__ edges,
                                                      const float* __restrict__ W2,
                                                      const float* __restrict__ b1,
                                                      const float* __restrict__ b2,
                                                      float* __restrict__ out,
                                                      int E, int tiles) {
    char* smem = smem_raw;
    __half* USh = (__half*)(smem + B_US);
    __half* VSh = (__half*)(smem + B_VS);
    __half* W2h = (__half*)(smem + B_W2);
    float*  b2s = (float*)(smem + B_B2);
    int*    eis = (int*)(smem + B_EIS);
    int*    ejs = (int*)(smem + B_EJS);

    int tid = threadIdx.x, wid = tid >> 5, lane = tid & 31;
    int rr = lane >> 2, q = lane & 3;
    int s = q & 1, tq = q >> 1;

    for (int idx = tid; idx < Hk * Dk; idx += 256) {
        int k = idx >> 6, n = idx & 63;
        int unit = (k & ~15) + c_p16[k & 15];
        W2h[n * PH + k] = __float2half(W2[unit * Dk + n]);
    }
    if (tid < Dk) b2s[tid] = b2[tid];

    __half2 b1lo[8], b1hi[8];
    #pragma unroll
    for (int g = 0; g < 8; g++) {
        b1lo[g] = __floats2half2_rn(b1[g * 16 + 2 * q],     b1[g * 16 + 2 * q + 1]);
        b1hi[g] = __floats2half2_rn(b1[g * 16 + 2 * q + 8], b1[g * 16 + 2 * q + 9]);
    }
    __syncthreads();

    int er0 = (wid & 3) * 32;
    int n0  = (wid >> 2) * 32;

    int l16 = lane & 15, h16 = lane >> 4;

    for (int t = blockIdx.x; t < tiles; t += gridDim.x) {
        int ebase = t * TE;
        if (tid < TE) {
            int e = ebase + tid;
            int a = 0, b = 0;
            if (e < E) { a = edges[2 * e]; b = edges[2 * e + 1]; }
            eis[tid] = a; ejs[tid] = b;
        }
        __syncthreads();

        #pragma unroll
        for (int dir = 0; dir < 2; dir++) {
            const int* sn = dir ? ejs : eis;
            const int* on = dir ? eis : ejs;

            #pragma unroll
            for (int r0 = wid * 16; r0 < wid * 16 + 16; r0 += 2) {
                int row = r0 + h16;
                const __half* up = g_U + (size_t)sn[row] * Hk;
                const __half* vp = g_V + (size_t)on[row] * Hk;
                cp_async16(USh + row * PH + l16 * 8, up + l16 * 8);
                cp_async16(VSh + row * PH + l16 * 8, vp + l16 * 8);
            }
            asm volatile("cp.async.commit_group;" ::: "memory");
            asm volatile("cp.async.wait_group 0;" ::: "memory");
            __syncthreads();

            float acc[2][4][4];
            #pragma unroll
            for (int mm = 0; mm < 2; mm++)
                #pragma unroll
                for (int j = 0; j < 4; j++)
                    #pragma unroll
                    for (int x = 0; x < 4; x++) acc[mm][j][x] = 0.f;

            #pragma unroll
            for (int g = 0; g < 8; g++) {
                int kof = g * 16 + 4 * q;
                uint32_t a[2][4];
                #pragma unroll
                for (int mm = 0; mm < 2; mm++) {
                    int base = (er0 + 16 * mm + rr) * PH + kof;
                    uint2 u0 = *(const uint2*)(USh + base);
                    uint2 v0 = *(const uint2*)(VSh + base);
                    uint2 u1 = *(const uint2*)(USh + base + 8 * PH);
                    uint2 v1 = *(const uint2*)(VSh + base + 8 * PH);
                    a[mm][0] = relu2add(u0.x, v0.x, b1lo[g]);
                    a[mm][2] = relu2add(u0.y, v0.y, b1hi[g]);
                    a[mm][1] = relu2add(u1.x, v1.x, b1lo[g]);
                    a[mm][3] = relu2add(u1.y, v1.y, b1hi[g]);
                }
                #pragma unroll
                for (int j = 0; j < 4; j++) {
                    uint2 bb = *(const uint2*)(W2h + (n0 + 8 * j + rr) * PH + kof);
                    #pragma unroll
                    for (int mm = 0; mm < 2; mm++)
                        mma_f16(acc[mm][j], a[mm][0], a[mm][1], a[mm][2], a[mm][3],
                                bb.x, bb.y);
                }
            }

            #pragma unroll
            for (int j = 0; j < 4; j++) {
                int nb = n0 + 8 * j + 2 * q;
                float bx = b2s[nb], by = b2s[nb + 1];
                #pragma unroll
                for (int mm = 0; mm < 2; mm++) {
                    acc[mm][j][0] += bx; acc[mm][j][1] += by;
                    acc[mm][j][2] += bx; acc[mm][j][3] += by;
                }
            }
            #pragma unroll
            for (int mm = 0; mm < 2; mm++) {
                int er = er0 + 16 * mm + rr + 8 * s;
                bool valid = (ebase + er) < E;
                int node = valid ? sn[er] : 0;
                float* base = out + (size_t)node * Dk;
                #pragma unroll
                for (int j = 0; j < 4; j++) {
                    float y0 = __shfl_xor_sync(0xffffffffu,
                                   s ? acc[mm][j][0] : acc[mm][j][2], 1);
                    float y1 = __shfl_xor_sync(0xffffffffu,
                                   s ? acc[mm][j][1] : acc[mm][j][3], 1);
                    float p0 = s ? y0 : acc[mm][j][0];
                    float p1 = s ? y1 : acc[mm][j][1];
                    float p2 = s ? acc[mm][j][2] : y0;
                    float p3 = s ? acc[mm][j][3] : y1;
                    if (valid) {
                        int nb = n0 + 8 * j + 4 * tq;
                        red_add_v4(base + nb, p0, p1, p2, p3);
                    }
                }
            }
            __syncthreads();
        }
    }
}

extern "C" void kernel_launch(void* const* d_in, const int* in_sizes, int n_in,
                              void* d_out, int out_size) {
    const float* nodes = (const float*)d_in[0];
    const int*   edges = (const int*)d_in[1];
    const float* W1    = (const float*)d_in[2];
    const float* b1    = (const float*)d_in[3];
    const float* W2    = (const float*)d_in[4];
    const float* b2    = (const float*)d_in[5];
    float* out = (float*)d_out;

    int N = in_sizes[0] / Dk;
    int E = in_sizes[1] / 2;

    static int nsm = 0;
    if (!nsm) {
        cudaDeviceGetAttribute(&nsm, cudaDevAttrMultiProcessorCount, 0);
        cudaFuncSetAttribute(uv_kernel,   cudaFuncAttributeMaxDynamicSharedMemorySize, UV_SMEM_BYTES);
        cudaFuncSetAttribute(edge_kernel, cudaFuncAttributeMaxDynamicSharedMemorySize, EDGE_SMEM_BYTES);
    }

    int total2 = N * 32;
    prep_nodes<<<(total2 + 255) / 256, 256>>>(nodes, out, total2);
    prep_w1<<<(256 * Dk + 255) / 256, 256>>>(W1);

    int uv_blocks = (N + 255) / 256;
    uv_kernel<<<uv_blocks, 256, UV_SMEM_BYTES>>>(N);

    int tiles = (E + TE - 1) / TE;
    edge_kernel<<<2 * nsm, 256, EDGE_SMEM_BYTES>>>(edges, W2, b1, b2, out, E, tiles);
}